// round 8
// baseline (speedup 1.0000x reference)
#include <cuda_runtime.h>
#include <cstddef>

#define IMG_W 256
#define IMG_H 256
#define RPB   64               // output rows per warp-strip
#define STEPS (RPB + 8)        // input rows S-4 .. S+RPB+3

// edge = conv(x,K5)+conv(x,K3) == 2.2*x - 0.19*box3(x) - 0.01*box5(x)
// out  = |maxpool5x5_s1_p2(edge)|   (separable; -inf pool padding)
//
// Vertical-first separable scheme. Persistent per-thread state: input ring
// 5x8, pool pair-chain 4x8, 2-deep prefetch. launch_bounds(128,3) -> 170-reg
// cap: fits the ~165-reg live set WITHOUT local-memory spills (the 128-reg
// cap of rounds 5-6 spilled ~40 slots; spill LDL/STL dominated L1).
// 12 warps/SM across all 4 SMSPs.

__global__ void __launch_bounds__(128, 3)
fused_edge_pool(const float* __restrict__ x, float* __restrict__ out)
{
    const int lane  = threadIdx.x & 31;
    const int g     = blockIdx.x * 4 + (threadIdx.x >> 5);   // 0..2047
    const int plane = g >> 2;                                // 512 planes
    const int S     = (g & 3) * RPB;                         // 4 strips/plane
    const int c0    = lane << 3;

    const float* __restrict__ xp = x   + (size_t)plane * (IMG_H * IMG_W) + c0;
    float*       __restrict__ op = out + (size_t)plane * (IMG_H * IMG_W) + c0;

    const float    NINF = __int_as_float(0xff800000);
    const unsigned FULL = 0xffffffffu;

    // Input ring: rows rin-4..rin, slot = row mod 5 (static via unroll-by-5).
    float xr[5][8];
#pragma unroll
    for (int i = 0; i < 5; ++i)
#pragma unroll
        for (int j = 0; j < 8; ++j) xr[i][j] = 0.f;

    // Vertical 5-max pair chain: out(r) = max(P3, P1, hm), P = max(hm_prev, hm).
    float hm_prev[8], P1[8], P2[8], P3[8];
#pragma unroll
    for (int j = 0; j < 8; ++j) { hm_prev[j] = P1[j] = P2[j] = P3[j] = NINF; }

    // 2-deep prefetch shift chain.
    float4 n0a, n0b, n1a, n1b;
    {
        const float4 z = make_float4(0.f, 0.f, 0.f, 0.f);
        int r0 = S - 4, r1 = S - 3;
        n0a = ((unsigned)r0 < IMG_H) ? *reinterpret_cast<const float4*>(xp + r0 * IMG_W)     : z;
        n0b = ((unsigned)r0 < IMG_H) ? *reinterpret_cast<const float4*>(xp + r0 * IMG_W + 4) : z;
        n1a = ((unsigned)r1 < IMG_H) ? *reinterpret_cast<const float4*>(xp + r1 * IMG_W)     : z;
        n1b = ((unsigned)r1 < IMG_H) ? *reinterpret_cast<const float4*>(xp + r1 * IMG_W + 4) : z;
    }

#pragma unroll 1
    for (int ss = 0; ss < STEPS; ss += 5) {
#pragma unroll
        for (int k = 0; k < 5; ++k) {
            const int s = ss + k;
            if (s >= STEPS) break;          // uniform across warp
            const int rin = S - 4 + s;      // input row consumed this step

            const float4 xa = n0a, xb = n0b;
            n0a = n1a; n0b = n1b;
            {
                const int rl = rin + 2;     // prefetch distance 2
                const bool v = ((unsigned)rl < IMG_H) && (s + 2 < STEPS);
                const float4 z = make_float4(0.f, 0.f, 0.f, 0.f);
                n1a = v ? *reinterpret_cast<const float4*>(xp + rl * IMG_W)     : z;
                n1b = v ? *reinterpret_cast<const float4*>(xp + rl * IMG_W + 4) : z;
            }

            // ---- write ring slot k (row rin) ----
            xr[k][0] = xa.x; xr[k][1] = xa.y; xr[k][2] = xa.z; xr[k][3] = xa.w;
            xr[k][4] = xb.x; xr[k][5] = xb.y; xr[k][6] = xb.z; xr[k][7] = xb.w;

            // ---- vertical box sums (edge row re = rin-2), into halo arrays ----
            const int a1 = (k + 4) % 5;   // rin-1
            const int a2 = (k + 3) % 5;   // rin-2 (center)
            const int a3 = (k + 2) % 5;   // rin-3
            const int a4 = (k + 1) % 5;   // rin-4
            float v3e[10];                // v3 at cols c0-1 .. c0+8
            float v5e[12];                // v5 at cols c0-2 .. c0+9
#pragma unroll
            for (int j = 0; j < 8; ++j) {
                const float t3 = xr[a1][j] + xr[a2][j] + xr[a3][j];
                v3e[j + 1] = t3;
                v5e[j + 2] = t3 + xr[k][j] + xr[a4][j];
            }

            // halos via shuffles
            v3e[0]  = __shfl_up_sync(FULL, v3e[8], 1);
            v3e[9]  = __shfl_down_sync(FULL, v3e[1], 1);
            v5e[0]  = __shfl_up_sync(FULL, v5e[8], 1);
            v5e[1]  = __shfl_up_sync(FULL, v5e[9], 1);
            v5e[10] = __shfl_down_sync(FULL, v5e[2], 1);
            v5e[11] = __shfl_down_sync(FULL, v5e[3], 1);
            if (lane == 0)  { v3e[0] = 0.f; v5e[0] = 0.f; v5e[1] = 0.f; }   // conv zero pad
            if (lane == 31) { v3e[9] = 0.f; v5e[10] = 0.f; v5e[11] = 0.f; }

            // ---- horizontal sums (pair tree) + edge, straight into q[2..9] ----
            float pm5[10];
#pragma unroll
            for (int i = 0; i < 10; ++i) pm5[i] = v5e[i] + v5e[i + 1];

            float q[12];
#pragma unroll
            for (int j = 0; j < 8; ++j) {
                const float h3 = v3e[j] + v3e[j + 1] + v3e[j + 2];
                const float h5 = pm5[j] + pm5[j + 2] + v5e[j + 4];
                q[j + 2] = fmaf(2.2f, xr[a2][j], fmaf(-0.19f, h3, -0.01f * h5));
            }

            // ---- horizontal 5-max halos ----
            q[0]  = __shfl_up_sync(FULL, q[8], 1);
            q[1]  = __shfl_up_sync(FULL, q[9], 1);
            q[10] = __shfl_down_sync(FULL, q[2], 1);
            q[11] = __shfl_down_sync(FULL, q[3], 1);
            if (lane == 0)  { q[0]  = NINF; q[1]  = NINF; }   // pool -inf pad
            if (lane == 31) { q[10] = NINF; q[11] = NINF; }

            float hm[8];
            const int re = rin - 2;
            if (re >= 0 && re < IMG_H) {     // warp-uniform; false only at strip edges
                float pm[10];
#pragma unroll
                for (int i = 0; i < 10; ++i) pm[i] = fmaxf(q[i], q[i + 1]);
#pragma unroll
                for (int j = 0; j < 8; ++j)
                    hm[j] = fmaxf(fmaxf(pm[j], pm[j + 2]), q[j + 4]);
            } else {
#pragma unroll
                for (int j = 0; j < 8; ++j) hm[j] = NINF;
            }

            // ---- vertical 5-max via pair chain + abs, output row r = rin-4 ----
            if (s >= 8) {
                const int r = rin - 4;
                float o[8];
#pragma unroll
                for (int j = 0; j < 8; ++j)
                    o[j] = fabsf(fmaxf(fmaxf(P3[j], P1[j]), hm[j]));
                *reinterpret_cast<float4*>(op + r * IMG_W)     = make_float4(o[0], o[1], o[2], o[3]);
                *reinterpret_cast<float4*>(op + r * IMG_W + 4) = make_float4(o[4], o[5], o[6], o[7]);
            }
#pragma unroll
            for (int j = 0; j < 8; ++j) {
                P3[j] = P2[j]; P2[j] = P1[j];
                P1[j] = fmaxf(hm_prev[j], hm[j]);
                hm_prev[j] = hm[j];
            }
        }
    }
}

extern "C" void kernel_launch(void* const* d_in, const int* in_sizes, int n_in,
                              void* d_out, int out_size)
{
    const float* x = (const float*)d_in[0];
    float* out = (float*)d_out;
    const int planes = in_sizes[0] / (IMG_H * IMG_W);          // 512
    const int warps  = planes * (IMG_H / RPB);                 // 2048
    fused_edge_pool<<<warps / 4, 128>>>(x, out);               // 512 blocks
}

// round 10
// speedup vs baseline: 1.6250x; 1.6250x over previous
#include <cuda_runtime.h>
#include <cstddef>
#include <cstdint>

#define IMG_W 256
#define IMG_H 256
#define RPB   64               // output rows per warp-strip
#define STEPS (RPB + 8)        // input rows S-4 .. S+RPB+3

// edge = conv(x,K5)+conv(x,K3) == 2.2*x - 0.19*box3(x) - 0.01*box5(x)
// out  = |maxpool5x5_s1_p2(edge)|   (separable; -inf pool padding)
//
// Vertical-first separable scheme. Persistent per-thread state: input ring
// 5x8 (40) + pool pair-chain 4x8 (32) ONLY. The register prefetch chain of
// earlier rounds is replaced by prefetch.global.L1 (no destination register)
// issued 3 rows ahead; the row LDG at use is then an L1 hit that ptxas can
// software-pipeline inside the unroll-by-5 body. Live set fits the 128-reg
// cap of launch_bounds(128,4) without local-memory spills -> 16 warps/SM.

__global__ void __launch_bounds__(128, 4)
fused_edge_pool(const float* __restrict__ x, float* __restrict__ out)
{
    const int lane  = threadIdx.x & 31;
    const int g     = blockIdx.x * 4 + (threadIdx.x >> 5);   // 0..2047
    const int plane = g >> 2;                                // 512 planes
    const int S     = (g & 3) * RPB;                         // 4 strips/plane
    const int c0    = lane << 3;

    const float* __restrict__ xp = x   + (size_t)plane * (IMG_H * IMG_W) + c0;
    float*       __restrict__ op = out + (size_t)plane * (IMG_H * IMG_W) + c0;

    const float    NINF = __int_as_float(0xff800000);
    const unsigned FULL = 0xffffffffu;

    // Input ring: rows rin-4..rin, slot = row mod 5 (static via unroll-by-5).
    float xr[5][8];
#pragma unroll
    for (int i = 0; i < 5; ++i)
#pragma unroll
        for (int j = 0; j < 8; ++j) xr[i][j] = 0.f;

    // Vertical 5-max pair chain: out(r) = max(P3, P1, hm), P = max(hm_prev, hm).
    float hm_prev[8], P1[8], P2[8], P3[8];
#pragma unroll
    for (int j = 0; j < 8; ++j) { hm_prev[j] = P1[j] = P2[j] = P3[j] = NINF; }

    // Warm the L1 with the first few rows (prefetch only; no registers).
    {
        int r0 = (S - 4 < 0) ? 0 : S - 4;
#pragma unroll
        for (int d = 0; d < 3; ++d) {
            int rp = r0 + d; if (rp > IMG_H - 1) rp = IMG_H - 1;
            const float* p = xp + rp * IMG_W;
            asm volatile("prefetch.global.L1 [%0];" :: "l"(p));
        }
    }

#pragma unroll 1
    for (int ss = 0; ss < STEPS; ss += 5) {
#pragma unroll
        for (int k = 0; k < 5; ++k) {
            const int s = ss + k;
            if (s >= STEPS) break;          // uniform across warp
            const int rin = S - 4 + s;      // input row consumed this step

            // L1 prefetch 3 rows ahead (clamped; covers this lane's 128B line).
            {
                int rp = rin + 3;
                rp = (rp < 0) ? 0 : (rp > IMG_H - 1 ? IMG_H - 1 : rp);
                const float* p = xp + rp * IMG_W;
                asm volatile("prefetch.global.L1 [%0];" :: "l"(p));
            }

            // Load row rin at use (L1 hit; pipelined across the 5-body).
            float4 xa, xb;
            if ((unsigned)rin < IMG_H) {    // warp-uniform
                xa = *reinterpret_cast<const float4*>(xp + rin * IMG_W);
                xb = *reinterpret_cast<const float4*>(xp + rin * IMG_W + 4);
            } else {
                xa = make_float4(0.f, 0.f, 0.f, 0.f);
                xb = make_float4(0.f, 0.f, 0.f, 0.f);
            }

            // ---- write ring slot k (row rin) ----
            xr[k][0] = xa.x; xr[k][1] = xa.y; xr[k][2] = xa.z; xr[k][3] = xa.w;
            xr[k][4] = xb.x; xr[k][5] = xb.y; xr[k][6] = xb.z; xr[k][7] = xb.w;

            // ---- vertical box sums (edge row re = rin-2), into halo arrays ----
            const int a1 = (k + 4) % 5;   // rin-1
            const int a2 = (k + 3) % 5;   // rin-2 (center)
            const int a3 = (k + 2) % 5;   // rin-3
            const int a4 = (k + 1) % 5;   // rin-4
            float v3e[10];                // v3 at cols c0-1 .. c0+8
            float v5e[12];                // v5 at cols c0-2 .. c0+9
#pragma unroll
            for (int j = 0; j < 8; ++j) {
                const float t3 = xr[a1][j] + xr[a2][j] + xr[a3][j];
                v3e[j + 1] = t3;
                v5e[j + 2] = t3 + xr[k][j] + xr[a4][j];
            }

            // halos via shuffles
            v3e[0]  = __shfl_up_sync(FULL, v3e[8], 1);
            v3e[9]  = __shfl_down_sync(FULL, v3e[1], 1);
            v5e[0]  = __shfl_up_sync(FULL, v5e[8], 1);
            v5e[1]  = __shfl_up_sync(FULL, v5e[9], 1);
            v5e[10] = __shfl_down_sync(FULL, v5e[2], 1);
            v5e[11] = __shfl_down_sync(FULL, v5e[3], 1);
            if (lane == 0)  { v3e[0] = 0.f; v5e[0] = 0.f; v5e[1] = 0.f; }   // conv zero pad
            if (lane == 31) { v3e[9] = 0.f; v5e[10] = 0.f; v5e[11] = 0.f; }

            // ---- horizontal sums (pair tree) + edge, straight into q[2..9] ----
            float pm5[10];
#pragma unroll
            for (int i = 0; i < 10; ++i) pm5[i] = v5e[i] + v5e[i + 1];

            float q[12];
#pragma unroll
            for (int j = 0; j < 8; ++j) {
                const float h3 = v3e[j] + v3e[j + 1] + v3e[j + 2];
                const float h5 = pm5[j] + pm5[j + 2] + v5e[j + 4];
                q[j + 2] = fmaf(2.2f, xr[a2][j], fmaf(-0.19f, h3, -0.01f * h5));
            }

            // ---- horizontal 5-max halos ----
            q[0]  = __shfl_up_sync(FULL, q[8], 1);
            q[1]  = __shfl_up_sync(FULL, q[9], 1);
            q[10] = __shfl_down_sync(FULL, q[2], 1);
            q[11] = __shfl_down_sync(FULL, q[3], 1);
            if (lane == 0)  { q[0]  = NINF; q[1]  = NINF; }   // pool -inf pad
            if (lane == 31) { q[10] = NINF; q[11] = NINF; }

            float hm[8];
            const int re = rin - 2;
            if (re >= 0 && re < IMG_H) {     // warp-uniform; false only at strip edges
                float pm[10];
#pragma unroll
                for (int i = 0; i < 10; ++i) pm[i] = fmaxf(q[i], q[i + 1]);
#pragma unroll
                for (int j = 0; j < 8; ++j)
                    hm[j] = fmaxf(fmaxf(pm[j], pm[j + 2]), q[j + 4]);
            } else {
#pragma unroll
                for (int j = 0; j < 8; ++j) hm[j] = NINF;
            }

            // ---- vertical 5-max via pair chain + abs, output row r = rin-4 ----
            if (s >= 8) {
                const int r = rin - 4;
                float o[8];
#pragma unroll
                for (int j = 0; j < 8; ++j)
                    o[j] = fabsf(fmaxf(fmaxf(P3[j], P1[j]), hm[j]));
                *reinterpret_cast<float4*>(op + r * IMG_W)     = make_float4(o[0], o[1], o[2], o[3]);
                *reinterpret_cast<float4*>(op + r * IMG_W + 4) = make_float4(o[4], o[5], o[6], o[7]);
            }
#pragma unroll
            for (int j = 0; j < 8; ++j) {
                P3[j] = P2[j]; P2[j] = P1[j];
                P1[j] = fmaxf(hm_prev[j], hm[j]);
                hm_prev[j] = hm[j];
            }
        }
    }
}

extern "C" void kernel_launch(void* const* d_in, const int* in_sizes, int n_in,
                              void* d_out, int out_size)
{
    const float* x = (const float*)d_in[0];
    float* out = (float*)d_out;
    const int planes = in_sizes[0] / (IMG_H * IMG_W);          // 512
    const int warps  = planes * (IMG_H / RPB);                 // 2048
    fused_edge_pool<<<warps / 4, 128>>>(x, out);               // 512 blocks, 1 wave
}

// round 12
// speedup vs baseline: 1.8021x; 1.1090x over previous
#include <cuda_runtime.h>
#include <cstddef>
#include <cstdint>

#define IMG_W 256
#define IMG_H 256
#define RPB   64               // output rows per warp-strip
#define STEPS (RPB + 8)        // input rows S-4 .. S+RPB+3

typedef unsigned long long ull;

// Packed f32x2 helpers (sm_103a): two independent fp32 lanes per 64-bit pair.
__device__ __forceinline__ ull addp(ull a, ull b) {
    ull d; asm("add.rn.f32x2 %0,%1,%2;" : "=l"(d) : "l"(a), "l"(b)); return d;
}
__device__ __forceinline__ ull mulp(ull a, ull b) {
    ull d; asm("mul.rn.f32x2 %0,%1,%2;" : "=l"(d) : "l"(a), "l"(b)); return d;
}
__device__ __forceinline__ ull fmap(ull a, ull b, ull c) {
    ull d; asm("fma.rn.f32x2 %0,%1,%2,%3;" : "=l"(d) : "l"(a), "l"(b), "l"(c)); return d;
}
__device__ __forceinline__ ull pk(float l, float h) {
    ull d; asm("mov.b64 %0,{%1,%2};" : "=l"(d) : "f"(l), "f"(h)); return d;
}
__device__ __forceinline__ float lof(ull a) { return __uint_as_float((unsigned)a); }
__device__ __forceinline__ float hif(ull a) { return __uint_as_float((unsigned)(a >> 32)); }

// edge = conv(x,K5)+conv(x,K3) == 2.2*x - 0.19*box3(x) - 0.01*box5(x)
// out  = |maxpool5x5_s1_p2(edge)|   (separable; -inf pool padding)
//
// Vertical-first separable scheme; ring kept as packed f32x2 pairs so the
// vertical box sums and the edge FMA stage run on packed math (halves those
// issue slots). Horizontal (shifted-index) stages stay scalar. L1 prefetch
// 3 rows ahead replaces any register prefetch state. 16 warps/SM, 1 wave.

__global__ void __launch_bounds__(128, 4)
fused_edge_pool(const float* __restrict__ x, float* __restrict__ out)
{
    const int lane  = threadIdx.x & 31;
    const int g     = blockIdx.x * 4 + (threadIdx.x >> 5);   // 0..2047
    const int plane = g >> 2;                                // 512 planes
    const int S     = (g & 3) * RPB;                         // 4 strips/plane
    const int c0    = lane << 3;

    const float* __restrict__ xp = x   + (size_t)plane * (IMG_H * IMG_W) + c0;
    float*       __restrict__ op = out + (size_t)plane * (IMG_H * IMG_W) + c0;

    const float    NINF = __int_as_float(0xff800000);
    const unsigned FULL = 0xffffffffu;

    const ull C22  = pk(2.2f, 2.2f);
    const ull CN19 = pk(-0.19f, -0.19f);
    const ull CN01 = pk(-0.01f, -0.01f);

    // Input ring, packed: rows rin-4..rin, 4 pairs (8 cols) per row.
    ull xr2[5][4];
#pragma unroll
    for (int i = 0; i < 5; ++i)
#pragma unroll
        for (int p = 0; p < 4; ++p) xr2[i][p] = 0ull;

    // Vertical 5-max pair chain: out(r) = max(P3, P1, hm), P = max(hm_prev, hm).
    float hm_prev[8], P1[8], P2[8], P3[8];
#pragma unroll
    for (int j = 0; j < 8; ++j) { hm_prev[j] = P1[j] = P2[j] = P3[j] = NINF; }

    // Warm L1 (register-free prefetch).
    {
        int r0 = (S - 4 < 0) ? 0 : S - 4;
#pragma unroll
        for (int d = 0; d < 3; ++d) {
            int rp = r0 + d; if (rp > IMG_H - 1) rp = IMG_H - 1;
            const float* p = xp + rp * IMG_W;
            asm volatile("prefetch.global.L1 [%0];" :: "l"(p));
        }
    }

#pragma unroll 1
    for (int ss = 0; ss < STEPS; ss += 5) {
#pragma unroll
        for (int k = 0; k < 5; ++k) {
            const int s = ss + k;
            if (s >= STEPS) break;          // uniform across warp
            const int rin = S - 4 + s;      // input row consumed this step

            // L1 prefetch 3 rows ahead (covers this lane's 128B line).
            {
                int rp = rin + 3;
                rp = (rp < 0) ? 0 : (rp > IMG_H - 1 ? IMG_H - 1 : rp);
                const float* p = xp + rp * IMG_W;
                asm volatile("prefetch.global.L1 [%0];" :: "l"(p));
            }

            // Load row rin (L1 hit) straight into packed pairs.
            if ((unsigned)rin < IMG_H) {    // warp-uniform
                const longlong2 la = *reinterpret_cast<const longlong2*>(xp + rin * IMG_W);
                const longlong2 lb = *reinterpret_cast<const longlong2*>(xp + rin * IMG_W + 4);
                xr2[k][0] = (ull)la.x; xr2[k][1] = (ull)la.y;
                xr2[k][2] = (ull)lb.x; xr2[k][3] = (ull)lb.y;
            } else {
                xr2[k][0] = 0ull; xr2[k][1] = 0ull; xr2[k][2] = 0ull; xr2[k][3] = 0ull;
            }

            // ---- vertical box sums (packed), edge row re = rin-2 ----
            const int a1 = (k + 4) % 5;   // rin-1
            const int a2 = (k + 3) % 5;   // rin-2 (center)
            const int a3 = (k + 2) % 5;   // rin-3
            const int a4 = (k + 1) % 5;   // rin-4
            float v3e[10];                // v3 at cols c0-1 .. c0+8
            float v5e[12];                // v5 at cols c0-2 .. c0+9
#pragma unroll
            for (int p = 0; p < 4; ++p) {
                const ull t3 = addp(addp(xr2[a1][p], xr2[a2][p]), xr2[a3][p]);
                const ull t5 = addp(addp(xr2[k][p], xr2[a4][p]), t3);
                v3e[2 * p + 1] = lof(t3);  v3e[2 * p + 2] = hif(t3);
                v5e[2 * p + 2] = lof(t5);  v5e[2 * p + 3] = hif(t5);
            }

            // halos via shuffles
            v3e[0]  = __shfl_up_sync(FULL, v3e[8], 1);
            v3e[9]  = __shfl_down_sync(FULL, v3e[1], 1);
            v5e[0]  = __shfl_up_sync(FULL, v5e[8], 1);
            v5e[1]  = __shfl_up_sync(FULL, v5e[9], 1);
            v5e[10] = __shfl_down_sync(FULL, v5e[2], 1);
            v5e[11] = __shfl_down_sync(FULL, v5e[3], 1);
            if (lane == 0)  { v3e[0] = 0.f; v5e[0] = 0.f; v5e[1] = 0.f; }   // conv zero pad
            if (lane == 31) { v3e[9] = 0.f; v5e[10] = 0.f; v5e[11] = 0.f; }

            // ---- horizontal sums (pair tree) + packed edge FMA -> q[2..9] ----
            float pm5[10];
#pragma unroll
            for (int i = 0; i < 10; ++i) pm5[i] = v5e[i] + v5e[i + 1];

            float q[12];
#pragma unroll
            for (int p = 0; p < 4; ++p) {
                const float h3lo = v3e[2 * p] + v3e[2 * p + 1] + v3e[2 * p + 2];
                const float h3hi = v3e[2 * p + 1] + v3e[2 * p + 2] + v3e[2 * p + 3];
                const float h5lo = pm5[2 * p] + pm5[2 * p + 2] + v5e[2 * p + 4];
                const float h5hi = pm5[2 * p + 1] + pm5[2 * p + 3] + v5e[2 * p + 5];
                const ull ep = fmap(C22, xr2[a2][p],
                                    fmap(CN19, pk(h3lo, h3hi),
                                         mulp(CN01, pk(h5lo, h5hi))));
                q[2 * p + 2] = lof(ep);  q[2 * p + 3] = hif(ep);
            }

            // ---- horizontal 5-max halos ----
            q[0]  = __shfl_up_sync(FULL, q[8], 1);
            q[1]  = __shfl_up_sync(FULL, q[9], 1);
            q[10] = __shfl_down_sync(FULL, q[2], 1);
            q[11] = __shfl_down_sync(FULL, q[3], 1);
            if (lane == 0)  { q[0]  = NINF; q[1]  = NINF; }   // pool -inf pad
            if (lane == 31) { q[10] = NINF; q[11] = NINF; }

            float hm[8];
            const int re = rin - 2;
            if (re >= 0 && re < IMG_H) {     // warp-uniform; false only at strip edges
                float pm[10];
#pragma unroll
                for (int i = 0; i < 10; ++i) pm[i] = fmaxf(q[i], q[i + 1]);
#pragma unroll
                for (int j = 0; j < 8; ++j)
                    hm[j] = fmaxf(fmaxf(pm[j], pm[j + 2]), q[j + 4]);
            } else {
#pragma unroll
                for (int j = 0; j < 8; ++j) hm[j] = NINF;
            }

            // ---- vertical 5-max via pair chain + abs, output row r = rin-4 ----
            if (s >= 8) {
                const int r = rin - 4;
                float o[8];
#pragma unroll
                for (int j = 0; j < 8; ++j)
                    o[j] = fabsf(fmaxf(fmaxf(P3[j], P1[j]), hm[j]));
                __stcs(reinterpret_cast<float4*>(op + r * IMG_W),
                       make_float4(o[0], o[1], o[2], o[3]));
                __stcs(reinterpret_cast<float4*>(op + r * IMG_W + 4),
                       make_float4(o[4], o[5], o[6], o[7]));
            }
#pragma unroll
            for (int j = 0; j < 8; ++j) {
                P3[j] = P2[j]; P2[j] = P1[j];
                P1[j] = fmaxf(hm_prev[j], hm[j]);
                hm_prev[j] = hm[j];
            }
        }
    }
}

extern "C" void kernel_launch(void* const* d_in, const int* in_sizes, int n_in,
                              void* d_out, int out_size)
{
    const float* x = (const float*)d_in[0];
    float* out = (float*)d_out;
    const int planes = in_sizes[0] / (IMG_H * IMG_W);          // 512
    const int warps  = planes * (IMG_H / RPB);                 // 2048
    fused_edge_pool<<<warps / 4, 128>>>(x, out);               // 512 blocks, 1 wave
}

// round 16
// speedup vs baseline: 1.8470x; 1.0249x over previous
#include <cuda_runtime.h>
#include <cstddef>
#include <cstdint>

#define IMG_W 256
#define IMG_H 256
#define RPB   64               // output rows per warp-strip
#define STEPS (RPB + 8)        // input rows S-4 .. S+RPB+3

typedef unsigned long long ull;

// Packed f32x2 helpers (sm_103a): two independent fp32 lanes per 64-bit pair.
__device__ __forceinline__ ull addp(ull a, ull b) {
    ull d; asm("add.rn.f32x2 %0,%1,%2;" : "=l"(d) : "l"(a), "l"(b)); return d;
}
__device__ __forceinline__ ull mulp(ull a, ull b) {
    ull d; asm("mul.rn.f32x2 %0,%1,%2;" : "=l"(d) : "l"(a), "l"(b)); return d;
}
__device__ __forceinline__ ull fmap(ull a, ull b, ull c) {
    ull d; asm("fma.rn.f32x2 %0,%1,%2,%3;" : "=l"(d) : "l"(a), "l"(b), "l"(c)); return d;
}
__device__ __forceinline__ ull pk(float l, float h) {
    ull d; asm("mov.b64 %0,{%1,%2};" : "=l"(d) : "f"(l), "f"(h)); return d;
}
__device__ __forceinline__ float lof(ull a) { return __uint_as_float((unsigned)a); }
__device__ __forceinline__ float hif(ull a) { return __uint_as_float((unsigned)(a >> 32)); }

// edge = conv(x,K5)+conv(x,K3) == 2.2*x - 0.19*box3(x) - 0.01*box5(x)
// out  = |maxpool5x5_s1_p2(edge)|   (separable; -inf pool padding)
//
// Vertical-first separable scheme, packed f32x2 math. Edge-stage refactor:
//   m = -0.19*v3 - 0.01*v5   (one packed FMA per pair)
//   edge = 2.2*x + H3(m) - 0.01*(v5[j-2]+v5[j+2])
// where the +-2 term is an ALIGNED packed pair add (W(p)=V5(p-1)+V5(p+1)),
// collapsing the old pm5-tree + h5/h3 combines (~42 slots) into ~28.
// L1 prefetch 3 rows ahead (register-free). 16 warps/SM, 1 wave.

__global__ void __launch_bounds__(128, 4)
fused_edge_pool(const float* __restrict__ x, float* __restrict__ out)
{
    const int lane  = threadIdx.x & 31;
    const int g     = blockIdx.x * 4 + (threadIdx.x >> 5);   // 0..2047
    const int plane = g >> 2;                                // 512 planes
    const int S     = (g & 3) * RPB;                         // 4 strips/plane
    const int c0    = lane << 3;

    const float* __restrict__ xp = x   + (size_t)plane * (IMG_H * IMG_W) + c0;
    float*       __restrict__ op = out + (size_t)plane * (IMG_H * IMG_W) + c0;

    const float    NINF = __int_as_float(0xff800000);
    const unsigned FULL = 0xffffffffu;

    const ull C22  = pk(2.2f, 2.2f);
    const ull CN19 = pk(-0.19f, -0.19f);
    const ull CN01 = pk(-0.01f, -0.01f);

    // Input ring, packed: rows rin-4..rin, 4 pairs (8 cols) per row.
    ull xr2[5][4];
#pragma unroll
    for (int i = 0; i < 5; ++i)
#pragma unroll
        for (int p = 0; p < 4; ++p) xr2[i][p] = 0ull;

    // Vertical 5-max pair chain: out(r) = max(P3, P1, hm), P = max(hm_prev, hm).
    float hm_prev[8], P1[8], P2[8], P3[8];
#pragma unroll
    for (int j = 0; j < 8; ++j) { hm_prev[j] = P1[j] = P2[j] = P3[j] = NINF; }

    // Warm L1 (register-free prefetch).
    {
        int r0 = (S - 4 < 0) ? 0 : S - 4;
#pragma unroll
        for (int d = 0; d < 3; ++d) {
            int rp = r0 + d; if (rp > IMG_H - 1) rp = IMG_H - 1;
            const float* p = xp + rp * IMG_W;
            asm volatile("prefetch.global.L1 [%0];" :: "l"(p));
        }
    }

#pragma unroll 1
    for (int ss = 0; ss < STEPS; ss += 5) {
#pragma unroll
        for (int k = 0; k < 5; ++k) {
            const int s = ss + k;
            if (s >= STEPS) break;          // uniform across warp
            const int rin = S - 4 + s;      // input row consumed this step

            // L1 prefetch 3 rows ahead (covers this lane's 128B line).
            {
                int rp = rin + 3;
                rp = (rp < 0) ? 0 : (rp > IMG_H - 1 ? IMG_H - 1 : rp);
                const float* p = xp + rp * IMG_W;
                asm volatile("prefetch.global.L1 [%0];" :: "l"(p));
            }

            // Load row rin (L1 hit) straight into packed pairs.
            if ((unsigned)rin < IMG_H) {    // warp-uniform
                const longlong2 la = *reinterpret_cast<const longlong2*>(xp + rin * IMG_W);
                const longlong2 lb = *reinterpret_cast<const longlong2*>(xp + rin * IMG_W + 4);
                xr2[k][0] = (ull)la.x; xr2[k][1] = (ull)la.y;
                xr2[k][2] = (ull)lb.x; xr2[k][3] = (ull)lb.y;
            } else {
                xr2[k][0] = 0ull; xr2[k][1] = 0ull; xr2[k][2] = 0ull; xr2[k][3] = 0ull;
            }

            // ---- vertical box sums (packed) + m = -0.19*v3 - 0.01*v5 ----
            const int a1 = (k + 4) % 5;   // rin-1
            const int a2 = (k + 3) % 5;   // rin-2 (center)
            const int a3 = (k + 2) % 5;   // rin-3
            const int a4 = (k + 1) % 5;   // rin-4
            ull V5[4], M[4];
#pragma unroll
            for (int p = 0; p < 4; ++p) {
                const ull t3 = addp(addp(xr2[a1][p], xr2[a2][p]), xr2[a3][p]);
                const ull t5 = addp(addp(xr2[k][p], xr2[a4][p]), t3);
                V5[p] = t5;
                M[p]  = fmap(CN19, t3, mulp(CN01, t5));
            }

            // ---- halos: m needs +-1 col, v5 needs +-1 PAIR (natural 64-bit) ----
            float mle = __shfl_up_sync(FULL, hif(M[3]), 1);    // m at col c0-1
            float mre = __shfl_down_sync(FULL, lof(M[0]), 1);  // m at col c0+8
            ull  v5l  = __shfl_up_sync(FULL, V5[3], 1);        // v5 cols c0-2,c0-1
            ull  v5r  = __shfl_down_sync(FULL, V5[0], 1);      // v5 cols c0+8,c0+9
            if (lane == 0)  { mle = 0.f; v5l = 0ull; }         // conv zero pad
            if (lane == 31) { mre = 0.f; v5r = 0ull; }

            // ---- W(p) = V5(p-1) + V5(p+1)  (aligned packed adds) ----
            ull W[4];
            W[0] = addp(v5l,   V5[1]);
            W[1] = addp(V5[0], V5[2]);
            W[2] = addp(V5[1], V5[3]);
            W[3] = addp(V5[2], v5r);

            // ---- H3(m) scalar, then edge = 2.2x + H3m - 0.01*W (packed) ----
            float me[10];
            me[0] = mle;
            me[1] = lof(M[0]); me[2] = hif(M[0]);
            me[3] = lof(M[1]); me[4] = hif(M[1]);
            me[5] = lof(M[2]); me[6] = hif(M[2]);
            me[7] = lof(M[3]); me[8] = hif(M[3]);
            me[9] = mre;

            float q[12];
#pragma unroll
            for (int p = 0; p < 4; ++p) {
                const float h3lo = me[2 * p]     + me[2 * p + 1] + me[2 * p + 2];
                const float h3hi = me[2 * p + 1] + me[2 * p + 2] + me[2 * p + 3];
                const ull ep = fmap(C22, xr2[a2][p],
                                    fmap(CN01, W[p], pk(h3lo, h3hi)));
                q[2 * p + 2] = lof(ep);  q[2 * p + 3] = hif(ep);
            }

            // ---- horizontal 5-max halos ----
            q[0]  = __shfl_up_sync(FULL, q[8], 1);
            q[1]  = __shfl_up_sync(FULL, q[9], 1);
            q[10] = __shfl_down_sync(FULL, q[2], 1);
            q[11] = __shfl_down_sync(FULL, q[3], 1);
            if (lane == 0)  { q[0]  = NINF; q[1]  = NINF; }   // pool -inf pad
            if (lane == 31) { q[10] = NINF; q[11] = NINF; }

            float hm[8];
            const int re = rin - 2;
            if (re >= 0 && re < IMG_H) {     // warp-uniform; false only at strip edges
                float pm[10];
#pragma unroll
                for (int i = 0; i < 10; ++i) pm[i] = fmaxf(q[i], q[i + 1]);
#pragma unroll
                for (int j = 0; j < 8; ++j)
                    hm[j] = fmaxf(fmaxf(pm[j], pm[j + 2]), q[j + 4]);
            } else {
#pragma unroll
                for (int j = 0; j < 8; ++j) hm[j] = NINF;
            }

            // ---- vertical 5-max via pair chain + abs, output row r = rin-4 ----
            if (s >= 8) {
                const int r = rin - 4;
                float o[8];
#pragma unroll
                for (int j = 0; j < 8; ++j)
                    o[j] = fabsf(fmaxf(fmaxf(P3[j], P1[j]), hm[j]));
                __stcs(reinterpret_cast<float4*>(op + r * IMG_W),
                       make_float4(o[0], o[1], o[2], o[3]));
                __stcs(reinterpret_cast<float4*>(op + r * IMG_W + 4),
                       make_float4(o[4], o[5], o[6], o[7]));
            }
#pragma unroll
            for (int j = 0; j < 8; ++j) {
                P3[j] = P2[j]; P2[j] = P1[j];
                P1[j] = fmaxf(hm_prev[j], hm[j]);
                hm_prev[j] = hm[j];
            }
        }
    }
}

extern "C" void kernel_launch(void* const* d_in, const int* in_sizes, int n_in,
                              void* d_out, int out_size)
{
    const float* x = (const float*)d_in[0];
    float* out = (float*)d_out;
    const int planes = in_sizes[0] / (IMG_H * IMG_W);          // 512
    const int warps  = planes * (IMG_H / RPB);                 // 2048
    fused_edge_pool<<<warps / 4, 128>>>(x, out);               // 512 blocks, 1 wave
}